// round 11
// baseline (speedup 1.0000x reference)
#include <cuda_runtime.h>
#include <cuda_bf16.h>

#define EPS 1e-6f
#define NB 16
#define NA 10
#define NT 30
#define NP_POLY 16
#define NV 200
#define SEG_PER_POLY (NV - 1)            // 199
#define NSEG (NP_POLY * SEG_PER_POLY)    // 3184 per batch
#define NPTS_WARP 10
#define WARPS 3
#define THREADS (WARPS * 32)             // 96: 3 warps x 10 pts = 30 = NT
#define NBA (NB * NA)                    // 160
#define GRID (NBA * NP_POLY)             // 2560
#define NSLOT (NBA * NT)                 // 4800

// per-(batch,segment) precomputed tables
__device__ float4 g_segA[NB * NSEG];  // {sx, sy, evx, evy}
__device__ float4 g_segB[NB * NSEG];  // {ey, 1/(esq+eps), 1/(slope+eps), 0}

// cross-poly folded slots (relaxed L2 atomics); zero-init, reset by folder
__device__ unsigned g_md[NSLOT];      // max of ~bits(d2) == min d2
__device__ int      g_ct[NSLOT];      // crossing counts
__device__ unsigned g_cnt[NBA];       // per-ba completion counters

__device__ __forceinline__ unsigned warp_redux_min_u32(unsigned v) {
    unsigned r;
    asm("redux.sync.min.u32 %0, %1, 0xffffffff;" : "=r"(r) : "r"(v));
    return r;
}
__device__ __forceinline__ int warp_redux_add_s32(int v) {
    int r;
    asm("redux.sync.add.s32 %0, %1, 0xffffffff;" : "=r"(r) : "r"(v));
    return r;
}
// release-only atomic: drains prior writes, should NOT invalidate L1
__device__ __forceinline__ unsigned atom_add_release(unsigned* p, unsigned v) {
    unsigned old;
    asm volatile("atom.release.gpu.global.add.u32 %0, [%1], %2;"
                 : "=r"(old) : "l"(p), "r"(v) : "memory");
    return old;
}
__device__ __forceinline__ void fence_acq() {
    asm volatile("fence.acq_rel.gpu;" ::: "memory");
}

__global__ void precompute_kernel(const float* __restrict__ polys) {
    int idx = blockIdx.x * blockDim.x + threadIdx.x;
    if (idx >= NB * NSEG) return;
    int b = idx / NSEG;
    int s = idx - b * NSEG;
    int p = s / SEG_PER_POLY;
    int j = s - p * SEG_PER_POLY;
    const float* v = polys + (((size_t)b * NP_POLY + p) * NV + j) * 2;
    float sx = v[0], sy = v[1], ex = v[2], ey = v[3];
    float evx = ex - sx;                    // same IEEE subs as reference
    float evy = ey - sy;
    float esq = fmaf(evx, evx, evy * evy);
    float rcp_esq = 1.0f / (esq + EPS);
    float slope = evy / (evx + EPS);
    float rcp_sl = 1.0f / (slope + EPS);
    g_segA[idx] = make_float4(sx, sy, evx, evy);
    g_segB[idx] = make_float4(ey, rcp_esq, rcp_sl, 0.0f);
}

__global__ __launch_bounds__(THREADS)
void offroad_main_kernel(const float* __restrict__ points,
                         float* __restrict__ out) {
    __shared__ int s_doFold;

    int bx = blockIdx.x;
    int p  = bx & (NP_POLY - 1);
    int ba = bx >> 4;                    // b*NA + a
    int b  = ba / NA;

    int wid = threadIdx.x >> 5;
    int ln  = threadIdx.x & 31;
    int t0  = wid * NPTS_WARP;           // 0,10,20 -> all valid

    float px[NPTS_WARP], py[NPTS_WARP], md[NPTS_WARP];
    int   ct[NPTS_WARP];

    const float2* pts2 = (const float2*)points;
#pragma unroll
    for (int k = 0; k < NPTS_WARP; k++) {
        float2 pt = pts2[ba * NT + t0 + k];
        px[k] = pt.x; py[k] = pt.y;
        md[k] = 3.4e38f;
        ct[k] = 0;
    }

    const float4* sA = g_segA + (b * NSEG + p * SEG_PER_POLY);
    const float4* sB = g_segB + (b * NSEG + p * SEG_PER_POLY);

#pragma unroll 1
    for (int s = ln; s < SEG_PER_POLY; s += 32) {
        float4 a = __ldg(&sA[s]);        // {sx, sy, evx, evy}
        float4 q = __ldg(&sB[s]);        // {ey, rcp_esq, rcp_sl, -}
#pragma unroll
        for (int k = 0; k < NPTS_WARP; k++) {
            float v1x = px[k] - a.x;
            float v1y = py[k] - a.y;
            float dot = fmaf(v1x, a.z, v1y * a.w);
            float proj = __saturatef(dot * q.y);
            float dx = fmaf(-a.z, proj, v1x);
            float dy = fmaf(-a.w, proj, v1y);
            float d2 = fmaf(dx, dx, dy * dy);
            md[k] = fminf(md[k], d2);
            bool c1 = (a.y <= py[k]);
            bool c2 = (q.x <= py[k]);
            float ix = fmaf(v1y, q.z, a.x);
            ct[k] += ((c1 != c2) & (ix > px[k])) ? 1 : 0;
        }
    }

    // warp fold (redux), then cross-block fold via RELAXED L2 atomics (no fence)
#pragma unroll
    for (int k = 0; k < NPTS_WARP; k++) {
        unsigned mb = warp_redux_min_u32(__float_as_uint(md[k]));  // d2>=0: bit-min == fmin
        int      cc = warp_redux_add_s32(ct[k]);
        if (ln == 0) {
            int idx = ba * NT + t0 + k;
            atomicMax(&g_md[idx], ~mb);          // RED.MAX, relaxed
            if (cc) atomicAdd(&g_ct[idx], cc);   // RED.ADD, relaxed
        }
    }

    // per-ba completion: release-only counter bump (no L1 invalidate expected)
    __syncthreads();
    if (threadIdx.x == 0) {
        unsigned old = atom_add_release(&g_cnt[ba], 1u);
        s_doFold = (old == (unsigned)(NP_POLY - 1));
    }
    __syncthreads();

    // 16th arriver finishes this ba (acquire fence only here: 160 blocks total)
    if (s_doFold && wid == 0) {
        fence_acq();
        float loss = 0.0f;
        if (ln < NT) {
            int idx = ba * NT + ln;
            unsigned mraw = g_md[idx];
            int cc = g_ct[idx];
            float m = __uint_as_float(~mraw);
            float d = sqrtf(fmaxf(m, EPS));
            if (cc & 1) d = -d;
            loss = fmaxf(d + 0.5f, 0.0f);
            // reset slots for next graph replay
            g_md[idx] = 0u;
            g_ct[idx] = 0;
        }
        if (ln == 0) g_cnt[ba] = 0;
        // deterministic fixed-tree sum over t (lanes 30,31 contribute 0)
#pragma unroll
        for (int o = 16; o > 0; o >>= 1)
            loss += __shfl_xor_sync(0xffffffffu, loss, o);
        if (ln == 0) out[ba] = loss;
    }
}

extern "C" void kernel_launch(void* const* d_in, const int* in_sizes, int n_in,
                              void* d_out, int out_size) {
    const float* points = (const float*)d_in[0];  // (16,10,30,2)
    const float* polys  = (const float*)d_in[1];  // (16,16,200,2)
    float* out = (float*)d_out;                   // (16,10)

    int total = NB * NSEG;
    precompute_kernel<<<(total + 255) / 256, 256>>>(polys);
    offroad_main_kernel<<<GRID, THREADS>>>(points, out);
}

// round 12
// speedup vs baseline: 1.1098x; 1.1098x over previous
#include <cuda_runtime.h>
#include <cuda_bf16.h>

#define EPS 1e-6f
#define NB 16
#define NA 10
#define NT 30
#define NP_POLY 16
#define NV 200
#define SEG_PER_POLY (NV - 1)            // 199
#define NSEG (NP_POLY * SEG_PER_POLY)    // 3184 per batch
#define NPTS_WARP 10
#define NPAIR (NPTS_WARP / 2)            // 5
#define WARPS 3
#define THREADS (WARPS * 32)             // 96
#define NBA (NB * NA)                    // 160
#define GRID (NBA * NP_POLY)             // 2560

typedef unsigned long long ull;

// packed f32x2 helpers (sm_100+)
#define ADD2(d, a, b)    asm("add.rn.f32x2 %0, %1, %2;"      : "=l"(d) : "l"(a), "l"(b))
#define MUL2(d, a, b)    asm("mul.rn.f32x2 %0, %1, %2;"      : "=l"(d) : "l"(a), "l"(b))
#define FMA2(d, a, b, c) asm("fma.rn.f32x2 %0, %1, %2, %3;"  : "=l"(d) : "l"(a), "l"(b), "l"(c))
#define PACK2(d, lo, hi) asm("mov.b64 %0, {%1, %2};"         : "=l"(d) : "f"(lo), "f"(hi))
#define UNPACK2(lo, hi, s) asm("mov.b64 {%0, %1}, %2;"       : "=f"(lo), "=f"(hi) : "l"(s))

// per-(batch,segment) precomputed tables
__device__ float4 g_segA[NB * NSEG];  // {sx, sy, evx, evy}
__device__ float4 g_segB[NB * NSEG];  // {ey, rcp_esq, c1=rcp_sl, c0=sx - sy*rcp_sl}

// partial results: [ba][t][poly]  (poly contiguous)
__device__ float g_md[NBA * NT * NP_POLY];
__device__ int   g_ct[NBA * NT * NP_POLY];

__device__ __forceinline__ void pdl_wait() {
    asm volatile("griddepcontrol.wait;" ::: "memory");
}
__device__ __forceinline__ void pdl_trigger() {
    asm volatile("griddepcontrol.launch_dependents;" ::: "memory");
}

__global__ void precompute_kernel(const float* __restrict__ polys) {
    int idx = blockIdx.x * blockDim.x + threadIdx.x;
    if (idx >= NB * NSEG) return;
    int b = idx / NSEG;
    int s = idx - b * NSEG;
    int p = s / SEG_PER_POLY;
    int j = s - p * SEG_PER_POLY;
    const float* v = polys + (((size_t)b * NP_POLY + p) * NV + j) * 2;
    float sx = v[0], sy = v[1], ex = v[2], ey = v[3];
    float evx = ex - sx;                    // same IEEE subs as reference
    float evy = ey - sy;
    float esq = fmaf(evx, evx, evy * evy);
    float rcp_esq = 1.0f / (esq + EPS);
    float slope = evy / (evx + EPS);
    float rcp_sl = 1.0f / (slope + EPS);
    float c0 = fmaf(-sy, rcp_sl, sx);       // intersect_x = py*rcp_sl + c0
    g_segA[idx] = make_float4(sx, sy, evx, evy);
    g_segB[idx] = make_float4(ey, rcp_esq, rcp_sl, c0);
}

__global__ __launch_bounds__(THREADS)
void offroad_main_kernel(const float* __restrict__ points) {
    int bx = blockIdx.x;
    int p  = bx & (NP_POLY - 1);
    int ba = bx >> 4;                    // b*NA + a
    int b  = ba / NA;

    int wid = threadIdx.x >> 5;
    int ln  = threadIdx.x & 31;
    int t0  = wid * NPTS_WARP;           // 0,10,20

    // packed point coords: 5 pairs of (x,x) and (y,y)
    ull px2[NPAIR], py2[NPAIR];
    float md[NPTS_WARP];
    int   ct[NPTS_WARP];

    const float2* pts2 = (const float2*)points;
#pragma unroll
    for (int j = 0; j < NPAIR; j++) {
        float2 p0 = pts2[ba * NT + t0 + 2 * j];
        float2 p1 = pts2[ba * NT + t0 + 2 * j + 1];
        PACK2(px2[j], p0.x, p1.x);
        PACK2(py2[j], p0.y, p1.y);
    }
#pragma unroll
    for (int k = 0; k < NPTS_WARP; k++) { md[k] = 3.4e38f; ct[k] = 0; }

    // gate only table reads on precompute completion
    pdl_wait();

    const float4* sA = g_segA + (b * NSEG + p * SEG_PER_POLY);
    const float4* sB = g_segB + (b * NSEG + p * SEG_PER_POLY);

#pragma unroll 1
    for (int s = ln; s < SEG_PER_POLY; s += 32) {
        float4 a = __ldg(&sA[s]);        // {sx, sy, evx, evy}
        float4 q = __ldg(&sB[s]);        // {ey, rcp_esq, rcp_sl, c0}

        // per-segment broadcast pairs
        float nsx = -a.x, nsy = -a.y, nevx = -a.z, nevy = -a.w, ney = -q.x;
        ull nsx2, nsy2, evx2, evy2, nevx2, nevy2, ney2, c12, c02;
        PACK2(nsx2,  nsx,  nsx);  PACK2(nsy2,  nsy,  nsy);
        PACK2(evx2,  a.z,  a.z);  PACK2(evy2,  a.w,  a.w);
        PACK2(nevx2, nevx, nevx); PACK2(nevy2, nevy, nevy);
        PACK2(ney2,  ney,  ney);
        PACK2(c12,   q.z,  q.z);  PACK2(c02,   q.w,  q.w);

#pragma unroll
        for (int j = 0; j < NPAIR; j++) {
            ull v1x2, v1y2, tt, dot2, pr2, dx2, dy2, t2, dd2, wy2, ix2;
            ADD2(v1x2, px2[j], nsx2);                 // px - sx
            ADD2(v1y2, py2[j], nsy2);                 // py - sy
            MUL2(tt, v1y2, evy2);
            FMA2(dot2, v1x2, evx2, tt);               // dot
            float d0, d1;
            UNPACK2(d0, d1, dot2);
            float pj0 = __saturatef(d0 * q.y);        // clamp(dot*rcp_esq, 0, 1)
            float pj1 = __saturatef(d1 * q.y);
            PACK2(pr2, pj0, pj1);
            FMA2(dx2, nevx2, pr2, v1x2);              // v1x - evx*proj
            FMA2(dy2, nevy2, pr2, v1y2);
            MUL2(t2, dy2, dy2);
            FMA2(dd2, dx2, dx2, t2);                  // d2
            float e0, e1;
            UNPACK2(e0, e1, dd2);
            md[2 * j]     = fminf(md[2 * j],     e0);
            md[2 * j + 1] = fminf(md[2 * j + 1], e1);

            // crossing: cond_y = signbit(py-sy) != signbit(py-ey)  (sign-exact)
            ADD2(wy2, py2[j], ney2);                  // py - ey
            FMA2(ix2, py2[j], c12, c02);              // intersect_x
            float vy0, vy1, wy0, wy1, ix0, ix1, qx0, qx1;
            UNPACK2(vy0, vy1, v1y2);
            UNPACK2(wy0, wy1, wy2);
            UNPACK2(ix0, ix1, ix2);
            UNPACK2(qx0, qx1, px2[j]);
            bool cy0 = ((__float_as_int(vy0) ^ __float_as_int(wy0)) < 0);
            bool cy1 = ((__float_as_int(vy1) ^ __float_as_int(wy1)) < 0);
            ct[2 * j]     += (cy0 & (ix0 > qx0)) ? 1 : 0;
            ct[2 * j + 1] += (cy1 & (ix1 > qx1)) ? 1 : 0;
        }
    }

    // warp reduction (champion butterfly)
#pragma unroll
    for (int k = 0; k < NPTS_WARP; k++) {
#pragma unroll
        for (int o = 16; o > 0; o >>= 1) {
            md[k] = fminf(md[k], __shfl_xor_sync(0xffffffffu, md[k], o));
            ct[k] += __shfl_xor_sync(0xffffffffu, ct[k], o);
        }
    }

    if (ln == 0) {
#pragma unroll
        for (int k = 0; k < NPTS_WARP; k++) {
            int idx = (ba * NT + t0 + k) * NP_POLY + p;
            g_md[idx] = md[k];
            g_ct[idx] = ct[k];
        }
    }

    __syncthreads();
    pdl_trigger();
}

__global__ __launch_bounds__(32)
void reduce_kernel(float* __restrict__ out) {
    int ba = blockIdx.x;   // 0..159
    int t  = threadIdx.x;  // 0..31

    pdl_wait();

    float loss = 0.0f;
    if (t < NT) {
        float md = 3.4e38f;
        int ct = 0;
        const float4* pm = (const float4*)(g_md + (ba * NT + t) * NP_POLY);
        const int4*   pc = (const int4*)  (g_ct + (ba * NT + t) * NP_POLY);
#pragma unroll
        for (int q = 0; q < NP_POLY / 4; q++) {
            float4 mv = pm[q];
            int4   cv = pc[q];
            md = fminf(md, fminf(fminf(mv.x, mv.y), fminf(mv.z, mv.w)));
            ct += cv.x + cv.y + cv.z + cv.w;
        }
        float d = sqrtf(fmaxf(md, EPS));
        if (ct & 1) d = -d;
        loss = fmaxf(d + 0.5f, 0.0f);
    }
#pragma unroll
    for (int o = 16; o > 0; o >>= 1)
        loss += __shfl_xor_sync(0xffffffffu, loss, o);
    if (t == 0) out[ba] = loss;
}

extern "C" void kernel_launch(void* const* d_in, const int* in_sizes, int n_in,
                              void* d_out, int out_size) {
    const float* points = (const float*)d_in[0];  // (16,10,30,2)
    const float* polys  = (const float*)d_in[1];  // (16,16,200,2)
    float* out = (float*)d_out;                   // (16,10)

    int total = NB * NSEG;
    precompute_kernel<<<(total + 255) / 256, 256>>>(polys);

    cudaLaunchAttribute attr[1];
    attr[0].id = cudaLaunchAttributeProgrammaticStreamSerialization;
    attr[0].val.programmaticStreamSerializationAllowed = 1;

    cudaLaunchConfig_t cfg_main = {};
    cfg_main.gridDim  = dim3(GRID, 1, 1);
    cfg_main.blockDim = dim3(THREADS, 1, 1);
    cfg_main.attrs = attr;
    cfg_main.numAttrs = 1;
    cudaLaunchKernelEx(&cfg_main, offroad_main_kernel, points);

    cudaLaunchConfig_t cfg_red = {};
    cfg_red.gridDim  = dim3(NBA, 1, 1);
    cfg_red.blockDim = dim3(32, 1, 1);
    cfg_red.attrs = attr;
    cfg_red.numAttrs = 1;
    cudaLaunchKernelEx(&cfg_red, reduce_kernel, out);
}